// round 1
// baseline (speedup 1.0000x reference)
#include <cuda_runtime.h>

#define BB 16
#define CC 256
#define TT 4096
#define KCODES 1024
#define NTOK (BB*TT)          // 65536
#define QN (BB*CC*TT)         // 16777216

__device__ float  g_fnorm[NTOK];
__device__ float  g_enorm[KCODES];
__device__ int    g_idx[NTOK];
__device__ double g_loss;

__global__ void zero_loss_kernel() { g_loss = 0.0; }

// ||e_k||^2 for each codebook row (contiguous rows of 256 floats)
__global__ void enorm_kernel(const float* __restrict__ cb) {
    int k = blockIdx.x * blockDim.x + threadIdx.x;
    if (k >= KCODES) return;
    const float4* row = reinterpret_cast<const float4*>(cb + (size_t)k * CC);
    float s = 0.f;
    #pragma unroll
    for (int i = 0; i < CC / 4; i++) {
        float4 v = row[i];
        s += v.x * v.x + v.y * v.y + v.z * v.z + v.w * v.w;
    }
    g_enorm[k] = s;
}

// ||f_t||^2 per token. x is (B,C,T); token feature stride is T, but across a
// warp consecutive tokens give coalesced reads for each c.
__global__ void fnorm_kernel(const float* __restrict__ x) {
    int tok = blockIdx.x * blockDim.x + threadIdx.x;
    int b = tok >> 12;
    int t = tok & (TT - 1);
    const float* p = x + (size_t)b * CC * TT + t;
    float s = 0.f;
    #pragma unroll 8
    for (int c = 0; c < CC; c++) {
        float v = p[(size_t)c * TT];
        s += v * v;
    }
    g_fnorm[tok] = s;
}

// Fused GEMM + argmin.
// Block: 64 tokens x (all 1024 codes in tiles of 256). 256 threads (32 x-codes, 8 x-tokens).
// Each thread: 8 tokens x 8 codes microtile.
// dist = fl(fl(fnorm - 2*dot) + enorm)  -- replicates the reference rounding chain.
__global__ __launch_bounds__(256) void argmin_kernel(
    const float* __restrict__ x, const float* __restrict__ cb,
    float* __restrict__ out_idx)
{
    __shared__ float xs[16][64];
    __shared__ float cs[16][256];
    __shared__ unsigned long long sbest[64];

    const int tid = threadIdx.x;
    const int tx = tid & 31;   // code group
    const int ty = tid >> 5;   // token group
    const int token0 = blockIdx.x * 64;
    const float* xblk = x + (size_t)(token0 >> 12) * (CC * TT) + (token0 & (TT - 1));

    float fn[8];
    #pragma unroll
    for (int i = 0; i < 8; i++) fn[i] = g_fnorm[token0 + ty * 8 + i];

    float bestd[8];
    int   besti[8];
    #pragma unroll
    for (int i = 0; i < 8; i++) { bestd[i] = 3.4e38f; besti[i] = 0; }

    for (int nt = 0; nt < KCODES; nt += 256) {
        float acc[8][8];
        #pragma unroll
        for (int i = 0; i < 8; i++)
            #pragma unroll
            for (int j = 0; j < 8; j++) acc[i][j] = 0.f;

        for (int c0 = 0; c0 < CC; c0 += 16) {
            // load x tile: xs[k][m] = x[c0+k][token0+m]  (coalesced over m)
            #pragma unroll
            for (int r = 0; r < 4; r++) {
                int e = tid + 256 * r;
                int k = e >> 6, m = e & 63;
                xs[k][m] = xblk[(size_t)(c0 + k) * TT + m];
            }
            // load codebook tile transposed: cs[k][n] = cb[nt+n][c0+k]
            #pragma unroll
            for (int r = 0; r < 4; r++) {
                int v = tid + 256 * r;
                int n = v >> 2, q = v & 3;
                float4 f = *reinterpret_cast<const float4*>(
                    cb + (size_t)(nt + n) * CC + c0 + 4 * q);
                cs[4 * q + 0][n] = f.x;
                cs[4 * q + 1][n] = f.y;
                cs[4 * q + 2][n] = f.z;
                cs[4 * q + 3][n] = f.w;
            }
            __syncthreads();

            #pragma unroll
            for (int k = 0; k < 16; k++) {
                float4 a0 = *reinterpret_cast<const float4*>(&xs[k][ty * 8]);
                float4 a1 = *reinterpret_cast<const float4*>(&xs[k][ty * 8 + 4]);
                float4 b0 = *reinterpret_cast<const float4*>(&cs[k][tx * 8]);
                float4 b1 = *reinterpret_cast<const float4*>(&cs[k][tx * 8 + 4]);
                float a[8] = {a0.x, a0.y, a0.z, a0.w, a1.x, a1.y, a1.z, a1.w};
                float bv[8] = {b0.x, b0.y, b0.z, b0.w, b1.x, b1.y, b1.z, b1.w};
                #pragma unroll
                for (int i = 0; i < 8; i++)
                    #pragma unroll
                    for (int j = 0; j < 8; j++)
                        acc[i][j] = fmaf(a[i], bv[j], acc[i][j]);
            }
            __syncthreads();
        }

        // epilogue for this code tile: running argmin with reference rounding order
        #pragma unroll
        for (int j = 0; j < 8; j++) {
            int n = nt + tx * 8 + j;       // ascending -> strict '<' keeps lowest idx
            float en = g_enorm[n];
            #pragma unroll
            for (int i = 0; i < 8; i++) {
                float d = fn[i] - 2.0f * acc[i][j];  // 2*dot exact; single rounding
                d = d + en;                          // second rounding
                if (d < bestd[i]) { bestd[i] = d; besti[i] = n; }
            }
        }
    }

    // cross-thread reduction: min over (ordered(dist), idx) packed key
    if (tid < 64) sbest[tid] = ~0ull;
    __syncthreads();
    #pragma unroll
    for (int i = 0; i < 8; i++) {
        unsigned u = __float_as_uint(bestd[i]);
        u = (u & 0x80000000u) ? ~u : (u | 0x80000000u);
        unsigned long long key =
            ((unsigned long long)u << 32) | (unsigned)besti[i];
        atomicMin(&sbest[ty * 8 + i], key);
    }
    __syncthreads();
    if (tid < 64) {
        int idx = (int)(sbest[tid] & 0xffffffffu);
        g_idx[token0 + tid] = idx;
        if (out_idx) out_idx[token0 + tid] = (float)idx;
    }
}

// Gather codebook rows, transpose to (B,C,T), write quantized_st = x + (q - x)
// (replicating the straight-through rounding), and accumulate loss = sum((q-x)^2).
__global__ __launch_bounds__(256) void gather_kernel(
    const float* __restrict__ x, const float* __restrict__ cb,
    float* __restrict__ out_q)
{
    __shared__ float qs[32][257];   // padded: conflict-free column reads
    __shared__ int   sidx[32];
    __shared__ float red[8];

    const int tid = threadIdx.x;
    const int t0 = blockIdx.x * 32;
    const int b = blockIdx.y;

    if (tid < 32) sidx[tid] = g_idx[b * TT + t0 + tid];
    __syncthreads();

    // load 32 codebook rows (each 256 floats, coalesced)
    #pragma unroll
    for (int r = 0; r < 32; r++)
        qs[r][tid] = cb[(size_t)sidx[r] * CC + tid];
    __syncthreads();

    float lsum = 0.f;
    const float* xb = x + (size_t)b * CC * TT + t0;
    float* ob = out_q + (size_t)b * CC * TT + t0;
    #pragma unroll
    for (int r = 0; r < 32; r++) {
        int c = (tid >> 5) + 8 * r;
        int tj = tid & 31;
        float q = qs[tj][c];
        float xv = xb[(size_t)c * TT + tj];
        float diff = q - xv;          // rounded, as in reference
        lsum += diff * diff;
        ob[(size_t)c * TT + tj] = xv + diff;  // straight-through value
    }

    #pragma unroll
    for (int o = 16; o; o >>= 1) lsum += __shfl_down_sync(0xffffffffu, lsum, o);
    if ((tid & 31) == 0) red[tid >> 5] = lsum;
    __syncthreads();
    if (tid == 0) {
        float s = 0.f;
        #pragma unroll
        for (int i = 0; i < 8; i++) s += red[i];
        atomicAdd(&g_loss, (double)s);
    }
}

__global__ void finalize_kernel(float* out_loss) {
    *out_loss = (float)(1.25 * g_loss / (double)QN);
}

extern "C" void kernel_launch(void* const* d_in, const int* in_sizes, int n_in,
                              void* d_out, int out_size) {
    const float* x  = (const float*)d_in[0];
    const float* cb = (const float*)d_in[1];
    // defensive: detect swapped input order via sizes
    if (n_in >= 2 && in_sizes[0] == KCODES * CC && in_sizes[1] == QN) {
        const float* tmp = x; x = cb; cb = tmp;
    }

    float* out = (float*)d_out;
    float* out_q = out;
    float* out_idx = nullptr;
    float* out_loss = nullptr;
    if (out_size >= QN + NTOK)     out_idx  = out + QN;
    if (out_size >= QN + NTOK + 1) out_loss = out + QN + NTOK;

    zero_loss_kernel<<<1, 1>>>();
    enorm_kernel<<<KCODES / 256, 256>>>(cb);
    fnorm_kernel<<<NTOK / 256, 256>>>(x);
    argmin_kernel<<<NTOK / 64, 256>>>(x, cb, out_idx);
    gather_kernel<<<dim3(TT / 32, BB), 256>>>(x, cb, out_q);
    if (out_loss) finalize_kernel<<<1, 1>>>(out_loss);
}